// round 13
// baseline (speedup 1.0000x reference)
#include <cuda_runtime.h>
#include <cstdint>

#define DIAM   1024
#define NPIX   (DIAM * DIAM)
#define N_WL   31
#define NEL    (NPIX * N_WL)        // 32,505,856
#define VEC    8
#define NTH    (NEL / VEC)          // 4,063,232 = 15872 * 256 exactly
#define RADIUS 512

// Phase rotation: 2-step Cody-Waite reduction (fp32-exact vs reference phase)
// + hardware sincos on |r|<=pi/4 + quadrant fix via sign-bit XOR.
__device__ __forceinline__ void rot_sincos(float ph, float& s_out, float& c_out) {
    float j = rintf(__fmul_rn(ph, 0.63661977236758134f));
    float r = fmaf(j, -1.5707963705062866e+00f, ph);
    r       = fmaf(j,  4.3711390001862449e-08f, r);
    int qi  = (int)j;
    float sr, cr;
    __sincosf(r, &sr, &cr);
    bool odd = (qi & 1);
    float ss = odd ? cr : sr;
    float cc = odd ? sr : cr;
    s_out = __int_as_float(__float_as_int(ss) ^ ((qi << 30) & 0x80000000));
    c_out = __int_as_float(__float_as_int(cc) ^ (((qi + 1) << 30) & 0x80000000));
}

__global__ __launch_bounds__(256, 7)
void doe_kernel(const float* __restrict__ hw,     // height_map_weight [512]
                const float* __restrict__ fr,     // field_real [NEL]
                const float* __restrict__ fi,     // field_imag [NEL]
                const float* __restrict__ wl,     // wavelength [31]
                const float* __restrict__ noise,  // [NPIX]
                const float* __restrict__ rad,    // radius_distance [NPIX]
                float* __restrict__ out)          // [2*NEL]
{
    __shared__ float s_t[N_WL];   // k * delta_n per wavelength
    if (threadIdx.x < N_WL) {
        float l  = wl[threadIdx.x];
        float k  = __fdiv_rn(6.283185307179586f, l);
        float dn = __fsub_rn(__fadd_rn(1.5f, __fdiv_rn(4e-15f, __fmul_rn(l, l))), 1.0f);
        s_t[threadIdx.x] = __fmul_rn(k, dn);
    }
    __syncthreads();

    int q = blockIdx.x * blockDim.x + threadIdx.x;   // exact grid: q < NTH
    int e = q * VEC;
    unsigned p  = (unsigned)e / 31u;
    int      w0 = e - (int)(p * 31u);
    unsigned pB = p + (w0 > (N_WL - VEC));           // span may straddle one pixel

    // Ground-truth radius from the input (quantizer boundaries must match
    // the reference bit-for-bit; never recompute).
    float rA = rad[p];
    float rB = rad[pB];
    bool inA = (rA <= (float)RADIUS);
    bool inB = (rB <= (float)RADIUS);

    float4* oR = (float4*)(out + e);
    float4* oI = (float4*)(out + NEL + e);

    if (!inA && !inB) {
        float4 z = make_float4(0.f, 0.f, 0.f, 0.f);
        __stcs(oR,     z); __stcs(oR + 1, z);
        __stcs(oI,     z); __stcs(oI + 1, z);
        return;
    }

    // Front-batch streaming loads (evict-first; single-touch data)
    float4 fra = __ldcs((const float4*)(fr + e));
    float4 frb = __ldcs((const float4*)(fr + e) + 1);
    float4 fia = __ldcs((const float4*)(fi + e));
    float4 fib = __ldcs((const float4*)(fi + e) + 1);
    float nzA = noise[p];
    float nzB = noise[pB];

    // q_base_height with exact fp32 rounding (constant-folded)
    const float lam0 = 7e-07f;
    float n0 = __fadd_rn(1.5f, __fdiv_rn(4e-15f, __fmul_rn(lam0, lam0)));
    float qh = __fdiv_rn(lam0, __fsub_rn(n0, 1.0f));

    float hA = 0.0f, hB = 0.0f;
    if (inA) {
        int idx = min(max((int)ceilf(rA) - 1, 0), 511);
        float w = fminf(fmaxf(hw[idx], -1.0f), 1.0f);
        float tv = __fsub_rn(0.002f, __fmul_rn(qh, __fmul_rn(__fadd_rn(w, 1.0f), 0.5f)));
        hA = __fadd_rn(tv, nzA);
    }
    if (inB) {
        int idx = min(max((int)ceilf(rB) - 1, 0), 511);
        float w = fminf(fmaxf(hw[idx], -1.0f), 1.0f);
        float tv = __fsub_rn(0.002f, __fmul_rn(qh, __fmul_rn(__fadd_rn(w, 1.0f), 0.5f)));
        hB = __fadd_rn(tv, nzB);
    }

    float fv[8] = {fra.x, fra.y, fra.z, fra.w, frb.x, frb.y, frb.z, frb.w};
    float gv[8] = {fia.x, fia.y, fia.z, fia.w, fib.x, fib.y, fib.z, fib.w};

    if (inA && inB) {
        // ---- fast path: whole quad inside aperture, no per-element masking ----
        float o0[4], w_0[4];
        #pragma unroll
        for (int k = 0; k < 4; k++) {
            int  wli    = w0 + k;
            bool second = (wli >= N_WL);
            float h     = second ? hB : hA;
            float s, c;
            rot_sincos(__fmul_rn(s_t[second ? wli - N_WL : wli], h), s, c);
            o0[k]  = __fsub_rn(__fmul_rn(fv[k], c), __fmul_rn(gv[k], s));
            w_0[k] = __fadd_rn(__fmul_rn(fv[k], s), __fmul_rn(gv[k], c));
        }
        __stcs(oR, make_float4(o0[0], o0[1], o0[2], o0[3]));
        __stcs(oI, make_float4(w_0[0], w_0[1], w_0[2], w_0[3]));

        float o1[4], w_1[4];
        #pragma unroll
        for (int k = 4; k < 8; k++) {
            int  wli    = w0 + k;
            bool second = (wli >= N_WL);
            float h     = second ? hB : hA;
            float s, c;
            rot_sincos(__fmul_rn(s_t[second ? wli - N_WL : wli], h), s, c);
            o1[k - 4]  = __fsub_rn(__fmul_rn(fv[k], c), __fmul_rn(gv[k], s));
            w_1[k - 4] = __fadd_rn(__fmul_rn(fv[k], s), __fmul_rn(gv[k], c));
        }
        __stcs(oR + 1, make_float4(o1[0], o1[1], o1[2], o1[3]));
        __stcs(oI + 1, make_float4(w_1[0], w_1[1], w_1[2], w_1[3]));
    } else {
        // ---- boundary path: quad straddles the aperture edge (rare) ----
        float ov[8], wv[8];
        #pragma unroll
        for (int k = 0; k < 8; k++) {
            int  wli    = w0 + k;
            bool second = (wli >= N_WL);
            float h     = second ? hB : hA;
            bool  in    = second ? inB : inA;
            float s, c;
            rot_sincos(__fmul_rn(s_t[second ? wli - N_WL : wli], h), s, c);
            float o_r = __fsub_rn(__fmul_rn(fv[k], c), __fmul_rn(gv[k], s));
            float o_i = __fadd_rn(__fmul_rn(fv[k], s), __fmul_rn(gv[k], c));
            ov[k] = in ? o_r : 0.0f;
            wv[k] = in ? o_i : 0.0f;
        }
        __stcs(oR,     make_float4(ov[0], ov[1], ov[2], ov[3]));
        __stcs(oR + 1, make_float4(ov[4], ov[5], ov[6], ov[7]));
        __stcs(oI,     make_float4(wv[0], wv[1], wv[2], wv[3]));
        __stcs(oI + 1, make_float4(wv[4], wv[5], wv[6], wv[7]));
    }
}

extern "C" void kernel_launch(void* const* d_in, const int* in_sizes, int n_in,
                              void* d_out, int out_size) {
    const float* hw    = (const float*)d_in[0];  // height_map_weight
    const float* fr    = (const float*)d_in[1];  // field_real
    const float* fi    = (const float*)d_in[2];  // field_imag
    const float* wl    = (const float*)d_in[3];  // wavelength
    const float* noise = (const float*)d_in[4];  // noise
    const float* rad   = (const float*)d_in[5];  // radius_distance
    // d_in[6] aperture == (rad <= 512), recomputed from loaded rad (validated R3/R6/R9)

    doe_kernel<<<NTH / 256, 256>>>(hw, fr, fi, wl, noise, rad, (float*)d_out);
}

// round 14
// speedup vs baseline: 1.0613x; 1.0613x over previous
#include <cuda_runtime.h>
#include <cstdint>

#define DIAM   1024
#define NPIX   (DIAM * DIAM)
#define N_WL   31
#define NEL    (NPIX * N_WL)        // 32,505,856
#define VEC    8
#define NTH    (NEL / VEC)          // 4,063,232 = 15872 * 256 exactly
#define RADIUS 512

// Phase rotation: 2-step Cody-Waite reduction (fp32-exact vs reference phase)
// + hardware sincos on |r|<=pi/4 + quadrant fix via sign-bit XOR (bit-exact
// equivalent of the compare/negate form, fewer ALU ops).
__device__ __forceinline__ void rot_sincos(float ph, float& s_out, float& c_out) {
    float j = rintf(__fmul_rn(ph, 0.63661977236758134f));
    float r = fmaf(j, -1.5707963705062866e+00f, ph);
    r       = fmaf(j,  4.3711390001862449e-08f, r);
    int qi  = (int)j;
    float sr, cr;
    __sincosf(r, &sr, &cr);
    bool odd = (qi & 1);
    float ss = odd ? cr : sr;
    float cc = odd ? sr : cr;
    s_out = __int_as_float(__float_as_int(ss) ^ ((qi << 30) & 0x80000000));
    c_out = __int_as_float(__float_as_int(cc) ^ (((qi + 1) << 30) & 0x80000000));
}

__global__ __launch_bounds__(256)
void doe_kernel(const float* __restrict__ hw,     // height_map_weight [512]
                const float* __restrict__ fr,     // field_real [NEL]
                const float* __restrict__ fi,     // field_imag [NEL]
                const float* __restrict__ wl,     // wavelength [31]
                const float* __restrict__ noise,  // [NPIX]
                const float* __restrict__ rad,    // radius_distance [NPIX]
                float* __restrict__ out)          // [2*NEL]
{
    __shared__ float s_t[N_WL];   // k * delta_n per wavelength
    if (threadIdx.x < N_WL) {
        float l  = wl[threadIdx.x];
        float k  = __fdiv_rn(6.283185307179586f, l);
        float dn = __fsub_rn(__fadd_rn(1.5f, __fdiv_rn(4e-15f, __fmul_rn(l, l))), 1.0f);
        s_t[threadIdx.x] = __fmul_rn(k, dn);
    }
    __syncthreads();

    int q = blockIdx.x * blockDim.x + threadIdx.x;   // exact grid: q < NTH
    int e = q * VEC;
    unsigned p  = (unsigned)e / 31u;
    int      w0 = e - (int)(p * 31u);
    unsigned pB = p + (w0 > (N_WL - VEC));           // span may straddle one pixel

    // Ground-truth radius from the input (quantizer boundaries must match
    // the reference bit-for-bit; never recompute).
    float rA = rad[p];
    float rB = rad[pB];
    bool inA = (rA <= (float)RADIUS);
    bool inB = (rB <= (float)RADIUS);

    float4* oR = (float4*)(out + e);
    float4* oI = (float4*)(out + NEL + e);

    if (!inA && !inB) {
        float4 z = make_float4(0.f, 0.f, 0.f, 0.f);
        __stcs(oR,     z); __stcs(oR + 1, z);
        __stcs(oI,     z); __stcs(oI + 1, z);
        return;
    }

    // Front-batch streaming loads (evict-first; single-touch data)
    float4 fra = __ldcs((const float4*)(fr + e));
    float4 frb = __ldcs((const float4*)(fr + e) + 1);
    float4 fia = __ldcs((const float4*)(fi + e));
    float4 fib = __ldcs((const float4*)(fi + e) + 1);
    float nzA = noise[p];
    float nzB = noise[pB];

    // q_base_height with exact fp32 rounding (constant-folded)
    const float lam0 = 7e-07f;
    float n0 = __fadd_rn(1.5f, __fdiv_rn(4e-15f, __fmul_rn(lam0, lam0)));
    float qh = __fdiv_rn(lam0, __fsub_rn(n0, 1.0f));

    float hA = 0.0f, hB = 0.0f;
    if (inA) {
        int idx = min(max((int)ceilf(rA) - 1, 0), 511);
        float w = fminf(fmaxf(hw[idx], -1.0f), 1.0f);
        float tv = __fsub_rn(0.002f, __fmul_rn(qh, __fmul_rn(__fadd_rn(w, 1.0f), 0.5f)));
        hA = __fadd_rn(tv, nzA);
    }
    if (inB) {
        int idx = min(max((int)ceilf(rB) - 1, 0), 511);
        float w = fminf(fmaxf(hw[idx], -1.0f), 1.0f);
        float tv = __fsub_rn(0.002f, __fmul_rn(qh, __fmul_rn(__fadd_rn(w, 1.0f), 0.5f)));
        hB = __fadd_rn(tv, nzB);
    }

    float fv[8] = {fra.x, fra.y, fra.z, fra.w, frb.x, frb.y, frb.z, frb.w};
    float gv[8] = {fia.x, fia.y, fia.z, fia.w, fib.x, fib.y, fib.z, fib.w};
    float ov[8], wv[8];

    #pragma unroll
    for (int k = 0; k < VEC; k++) {
        int  wli    = w0 + k;
        bool second = (wli >= N_WL);
        int  wlm    = second ? wli - N_WL : wli;
        float h     = second ? hB : hA;
        bool  in    = second ? inB : inA;

        float s, c;
        rot_sincos(__fmul_rn(s_t[wlm], h), s, c);

        float o_r = __fsub_rn(__fmul_rn(fv[k], c), __fmul_rn(gv[k], s));
        float o_i = __fadd_rn(__fmul_rn(fv[k], s), __fmul_rn(gv[k], c));
        ov[k] = in ? o_r : 0.0f;
        wv[k] = in ? o_i : 0.0f;
    }

    __stcs(oR,     make_float4(ov[0], ov[1], ov[2], ov[3]));
    __stcs(oR + 1, make_float4(ov[4], ov[5], ov[6], ov[7]));
    __stcs(oI,     make_float4(wv[0], wv[1], wv[2], wv[3]));
    __stcs(oI + 1, make_float4(wv[4], wv[5], wv[6], wv[7]));
}

extern "C" void kernel_launch(void* const* d_in, const int* in_sizes, int n_in,
                              void* d_out, int out_size) {
    const float* hw    = (const float*)d_in[0];  // height_map_weight
    const float* fr    = (const float*)d_in[1];  // field_real
    const float* fi    = (const float*)d_in[2];  // field_imag
    const float* wl    = (const float*)d_in[3];  // wavelength
    const float* noise = (const float*)d_in[4];  // noise
    const float* rad   = (const float*)d_in[5];  // radius_distance
    // d_in[6] aperture == (rad <= 512), recomputed from loaded rad (validated R3/R6/R9)

    doe_kernel<<<NTH / 256, 256>>>(hw, fr, fi, wl, noise, rad, (float*)d_out);
}